// round 1
// baseline (speedup 1.0000x reference)
#include <cuda_runtime.h>
#include <cuda_bf16.h>

#define INF_F 1e30f
#define MAXD 8

__global__ __launch_bounds__(256)
void RmstWL_kernel(const float* __restrict__ pos,
                   const int*   __restrict__ flat_netpin,
                   const int*   __restrict__ netpin_start,
                   const int*   __restrict__ ignore_deg_ptr,
                   float*       __restrict__ out,
                   int n_nets, int num_pins)
{
    int i = blockIdx.x * blockDim.x + threadIdx.x;
    if (i >= n_nets) return;

    int s = netpin_start[i];
    int e = netpin_start[i + 1];
    int deg = e - s;
    int d = deg < MAXD ? deg : MAXD;

    // Gather pin coordinates. Indices are contiguous; coords are random gathers
    // (L2-resident working set). All arrays indexed only with unrolled
    // compile-time indices -> stay in registers.
    float px[MAXD], py[MAXD];
#pragma unroll
    for (int j = 0; j < MAXD; j++) {
        if (j < d) {
            int p = __ldg(&flat_netpin[s + j]);
            px[j] = __ldg(&pos[p]);
            py[j] = __ldg(&pos[num_pins + p]);
        } else {
            px[j] = 0.f; py[j] = 0.f;
        }
    }

    // Prim's MST with min-dist array. Node 0 starts in the tree.
    float md[MAXD];
#pragma unroll
    for (int j = 0; j < MAXD; j++) {
        md[j] = (j > 0 && j < d)
              ? fabsf(px[0] - px[j]) + fabsf(py[0] - py[j])
              : INF_F;
    }

    unsigned intree = 1u;   // bitmask of tree membership
    float total = 0.f;

    for (int it = 1; it < d; it++) {
        // argmin over non-tree nodes; capture winner's coords to avoid
        // runtime-indexing px/py (which would spill to local memory).
        float c = INF_F, bx = 0.f, by = 0.f;
        int best = 0;
#pragma unroll
        for (int j = 1; j < MAXD; j++) {
            bool cand = (j < d) && !((intree >> j) & 1u) && (md[j] < c);
            if (cand) { c = md[j]; best = j; bx = px[j]; by = py[j]; }
        }
        total += c;
        intree |= (1u << best);

        // Relax distances from the newly added node.
#pragma unroll
        for (int k = 1; k < MAXD; k++) {
            if (k < d && !((intree >> k) & 1u)) {
                float nd = fabsf(bx - px[k]) + fabsf(by - py[k]);
                md[k] = fminf(md[k], nd);
            }
        }
    }

    int ignore = __ldg(ignore_deg_ptr);   // first 4 bytes: works for i32 or LE i64
    out[i] = (deg >= 2 && deg <= ignore) ? total : 0.f;
}

extern "C" void kernel_launch(void* const* d_in, const int* in_sizes, int n_in,
                              void* d_out, int out_size)
{
    const float* pos          = (const float*)d_in[0];
    const int*   flat_netpin  = (const int*)  d_in[1];
    const int*   netpin_start = (const int*)  d_in[2];
    const int*   ignore_deg   = (const int*)  d_in[3];
    // d_in[4] = read_lut_flag (unused, matches reference)
    float* out = (float*)d_out;

    int num_pins = in_sizes[1];
    int n_nets   = in_sizes[2] - 1;

    int threads = 256;
    int blocks  = (n_nets + threads - 1) / threads;
    RmstWL_kernel<<<blocks, threads>>>(pos, flat_netpin, netpin_start,
                                       ignore_deg, out, n_nets, num_pins);
}